// round 5
// baseline (speedup 1.0000x reference)
#include <cuda_runtime.h>
#include <cuda_bf16.h>
#include <math.h>

// Problem constants (fixed by setup_inputs)
#define NPTS 32768
#define NV   10475
#define NJ   55
#define KNN  6

#define NQ    4              // template range split into quarters
#define QLEN  2624           // templates per quarter (4*2624 = 10496 >= NV)
#define VBLK  64             // threshold refresh period
#define BAT   16             // screen batch size
#define SEPS  1e-3f          // screening slack (>> fp32 rounding skew)

// Scratch (no cudaMalloc allowed): per-quarter top-6.
__device__ int   g_knn_idx[NQ * NPTS * KNN];
__device__ float g_knn_d  [NQ * NPTS * KNN];

// ---------------------------------------------------------------------------
// Kernel 1: screened KNN over one template quarter per CTA.
// 512 CTAs = 128 point-blocks x 4 quarters; 42KB smem -> 4 CTAs/SM
// -> 8 warps/SMSP for latency hiding.
// Hot loop: s = fma(pz,tz, fma(py,ty, fma(px,tx, -t2/2)))  (1 LDS.128 + 3 FFMA)
// Batch-of-16 max vs a threshold STALE within each 64-template block.
// Rare path: exact reference-rounded d2 (verified in R3/R4):
//   cross = fma(pz,tz, fma(py,ty, fl(px*tx)))
//   d2    = fma(-2, cross, fl(p2 + t2)),  t2 = -2*w (exact)
// ---------------------------------------------------------------------------
extern "C" __global__ void __launch_bounds__(256)
knn_kernel(const float* __restrict__ pts,      // (N,3)
           const float* __restrict__ tpts)     // (V,3)
{
    extern __shared__ float4 st[];   // QLEN float4 = 41984 B (padded req 47104)

    const int q    = blockIdx.x >> 7;        // quarter 0..3
    const int pblk = blockIdx.x & 127;       // point block 0..127
    const int vq0  = q * QLEN;               // global template base

    for (int v = threadIdx.x; v < QLEN; v += 256) {
        int vg = vq0 + v;
        if (vg < NV) {
            float x = tpts[3 * vg + 0];
            float y = tpts[3 * vg + 1];
            float z = tpts[3 * vg + 2];
            float t2 = __fadd_rn(__fadd_rn(__fmul_rn(x, x), __fmul_rn(y, y)),
                                 __fmul_rn(z, z));
            st[v] = make_float4(x, y, z, -0.5f * t2);   // exact halving
        } else {
            st[v] = make_float4(0.0f, 0.0f, 0.0f, -INFINITY);  // sentinel
        }
    }
    __syncthreads();

    const int n = pblk * 256 + threadIdx.x;

    float px = pts[3 * n + 0];
    float py = pts[3 * n + 1];
    float pz = pts[3 * n + 2];
    float p2 = __fadd_rn(__fadd_rn(__fmul_rn(px, px), __fmul_rn(py, py)),
                         __fmul_rn(pz, pz));

    float bd[KNN];     // best (smallest) exact d2 in this quarter, ascending
    int   bi[KNN];     // global indices
#pragma unroll
    for (int k = 0; k < KNN; ++k) { bd[k] = INFINITY; bi[k] = 0; }

    float s_thresh = -INFINITY;     // pass screen if s > s_thresh

#pragma unroll 1
    for (int vb = 0; vb < QLEN; vb += VBLK) {
#pragma unroll 1
        for (int v0 = vb; v0 < vb + VBLK; v0 += BAT) {
            float s[BAT];
#pragma unroll
            for (int i = 0; i < BAT; ++i) {
                float4 t = st[v0 + i];
                s[i] = fmaf(pz, t.z, fmaf(py, t.y, fmaf(px, t.x, t.w)));
            }
            // max tree over 16
            float m0 = fmaxf(fmaxf(s[0],  s[1]),  fmaxf(s[2],  s[3]));
            float m1 = fmaxf(fmaxf(s[4],  s[5]),  fmaxf(s[6],  s[7]));
            float m2 = fmaxf(fmaxf(s[8],  s[9]),  fmaxf(s[10], s[11]));
            float m3 = fmaxf(fmaxf(s[12], s[13]), fmaxf(s[14], s[15]));
            float m  = fmaxf(fmaxf(m0, m1), fmaxf(m2, m3));

            if (m > s_thresh) {     // rare after warmup
#pragma unroll
                for (int i = 0; i < BAT; ++i) {
                    if (s[i] > s_thresh) {
                        float4 t = st[v0 + i];
                        float t2 = -2.0f * t.w;                 // exact
                        float cross = __fmaf_rn(pz, t.z,
                                      __fmaf_rn(py, t.y,
                                      __fmul_rn(px, t.x)));
                        float d2 = __fmaf_rn(-2.0f, cross,
                                             __fadd_rn(p2, t2));
                        if (d2 < bd[KNN - 1]) {
                            bd[KNN - 1] = d2; bi[KNN - 1] = vq0 + v0 + i;
#pragma unroll
                            for (int k = KNN - 1; k > 0; --k) {
                                if (bd[k] < bd[k - 1]) {   // strict: tie-stable
                                    float td_ = bd[k]; bd[k] = bd[k-1]; bd[k-1] = td_;
                                    int   ti_ = bi[k]; bi[k] = bi[k-1]; bi[k-1] = ti_;
                                }
                            }
                        }
                    }
                }
            }
        }
        // Refresh stale threshold (d2 < bd[5]  <=>  s > (p2 - bd[5])/2)
        s_thresh = fmaf(-0.5f, bd[KNN - 1], 0.5f * p2) - SEPS;
    }

#pragma unroll
    for (int k = 0; k < KNN; ++k) {
        g_knn_idx[(q * NPTS + n) * KNN + k] = bi[k];
        g_knn_d  [(q * NPTS + n) * KNN + k] = fmaxf(bd[k], 0.0f);  // ref clamp
    }
}

// ---------------------------------------------------------------------------
// Kernel 2: merge 4 quarter-lists + full reference epilogue. One warp/point.
// ---------------------------------------------------------------------------
extern "C" __global__ void __launch_bounds__(256)
epilogue_kernel(const float* __restrict__ lbs,   // (V,55)
                const float* __restrict__ vt,    // (V,16)
                float* __restrict__ out)         // [N dist | N*16 transform]
{
    int gwarp = (blockIdx.x * blockDim.x + threadIdx.x) >> 5;
    int lane  = threadIdx.x & 31;

    // --- merge: lanes 0..23 hold (d2, idx) of quarter lane/6, slot lane%6 ---
    float md = INFINITY;
    int   mi = 0x7FFFFFFF;
    if (lane < NQ * KNN) {
        int qq = lane / KNN, sl = lane % KNN;
        md = g_knn_d  [(qq * NPTS + gwarp) * KNN + sl];
        mi = g_knn_idx[(qq * NPTS + gwarp) * KNN + sl];
    }

    int   idx[KNN];
    float d[KNN];
#pragma unroll
    for (int k = 0; k < KNN; ++k) {
        // lexicographic warp argmin over (d, idx)
        float cd = md; int ci = mi;
#pragma unroll
        for (int off = 16; off >= 1; off >>= 1) {
            float od = __shfl_xor_sync(0xFFFFFFFFu, cd, off);
            int   oi = __shfl_xor_sync(0xFFFFFFFFu, ci, off);
            if (od < cd || (od == cd && oi < ci)) { cd = od; ci = oi; }
        }
        d[k] = cd; idx[k] = ci;
        if (mi == ci) md = INFINITY;   // idx unique across lanes -> remove one
    }

    // --- reference epilogue ---
    const float* w0row = lbs + (long)idx[0] * NJ;
    float w0a = w0row[lane];
    float w0b = (lane < NJ - 32) ? w0row[lane + 32] : 0.0f;

    float conf[KNN];
    conf[0] = 1.0f;
#pragma unroll
    for (int k = 1; k < KNN; ++k) {
        const float* wr = lbs + (long)idx[k] * NJ;
        float a = fabsf(wr[lane] - w0a);
        if (lane < NJ - 32) a += fabsf(wr[lane + 32] - w0b);
#pragma unroll
        for (int off = 16; off >= 1; off >>= 1)
            a += __shfl_xor_sync(0xFFFFFFFFu, a, off);
        conf[k] = (expf(-a * (1.0f / 0.02f)) > 0.9f) ? 1.0f : 0.0f;
    }

    float w[KNN];
    float wsum = 0.0f;
#pragma unroll
    for (int k = 0; k < KNN; ++k) {
        w[k] = expf(-d[k]) * conf[k];
        wsum += w[k];
    }
    float inv = 1.0f / wsum;

    float xd  = 0.0f;
    float acc = 0.0f;
#pragma unroll
    for (int k = 0; k < KNN; ++k) {
        float wk = w[k] * inv;
        xd = fmaf(wk, d[k], xd);
        if (lane < 16)
            acc = fmaf(wk, vt[(long)idx[k] * 16 + lane], acc);
    }

    if (lane == 0) out[gwarp] = xd;
    if (lane < 16) out[NPTS + gwarp * 16 + lane] = acc;
}

// ---------------------------------------------------------------------------
// Launch. Inputs: lbs_weights, verts_transform, points, template_points, K.
// ---------------------------------------------------------------------------
extern "C" void kernel_launch(void* const* d_in, const int* in_sizes, int n_in,
                              void* d_out, int out_size)
{
    const float* lbs  = (const float*)d_in[0];
    const float* vt   = (const float*)d_in[1];
    const float* pts  = (const float*)d_in[2];
    const float* tpts = (const float*)d_in[3];
    float* out = (float*)d_out;

    // 42KB needed; request 46KB so exactly 4 CTAs/SM (228/46 -> 4).
    const int smem_bytes = 47104;
    cudaFuncSetAttribute(knn_kernel,
                         cudaFuncAttributeMaxDynamicSharedMemorySize,
                         smem_bytes);

    knn_kernel<<<128 * NQ, 256, smem_bytes>>>(pts, tpts);
    epilogue_kernel<<<(NPTS * 32) / 256, 256>>>(lbs, vt, out);
}